// round 1
// baseline (speedup 1.0000x reference)
#include <cuda_runtime.h>
#include <cuda_bf16.h>

// Problem dims (fixed by the dataset)
#define T_TOK 8192   // B*S = 4*2048 tokens
#define H_DIM 2048
#define I_DIM 8192
#define NW    16777216  // elements per weight matrix (I*H == H*I)

// ---------------- device scratch (static allocations only) ----------------
__device__ float       g_part[3 * 1024];       // per-block |w| partial sums
__device__ float       g_wnorm[3];             // clipped mean|w| (= 1/scale_w)
__device__ signed char g_wqg[NW];              // ternary w_gate
__device__ signed char g_wqu[NW];              // ternary w_up
__device__ signed char g_wqd[NW];              // ternary w_down
__device__ signed char g_xq[T_TOK * H_DIM];    // int8 quantized x
__device__ float       g_xs[T_TOK];            // act scale #1 (128/max|x|)
__device__ float       g_inter[67108864];      // fp32 silu(gate)*up  [T,I]
__device__ signed char g_aq2[67108864];        // int8 quantized fwht(inter)
__device__ float       g_as2[T_TOK];           // act scale #2

// ---------------- helpers ----------------
__device__ __forceinline__ int pack_q4(float4 v, float s, float lo, float hi) {
    int q0 = (int)fminf(fmaxf(rintf(v.x * s), lo), hi);
    int q1 = (int)fminf(fmaxf(rintf(v.y * s), lo), hi);
    int q2 = (int)fminf(fmaxf(rintf(v.z * s), lo), hi);
    int q3 = (int)fminf(fmaxf(rintf(v.w * s), lo), hi);
    return (q0 & 0xff) | ((q1 & 0xff) << 8) | ((q2 & 0xff) << 16) | ((q3 & 0xff) << 24);
}

// ---------------- 1) |w| partial reduction (deterministic, no atomics) ----
__global__ void k_wabs(const float* __restrict__ w0, const float* __restrict__ w1,
                       const float* __restrict__ w2) {
    __shared__ float red[256];
    const float* W = (blockIdx.y == 0) ? w0 : ((blockIdx.y == 1) ? w1 : w2);
    float s = 0.f;
    for (int idx = blockIdx.x * 256 + threadIdx.x; idx < NW / 4; idx += 1024 * 256) {
        float4 v = reinterpret_cast<const float4*>(W)[idx];
        s += fabsf(v.x) + fabsf(v.y) + fabsf(v.z) + fabsf(v.w);
    }
    red[threadIdx.x] = s;
    __syncthreads();
    for (int o = 128; o > 0; o >>= 1) {
        if (threadIdx.x < o) red[threadIdx.x] += red[threadIdx.x + o];
        __syncthreads();
    }
    if (threadIdx.x == 0) g_part[blockIdx.y * 1024 + blockIdx.x] = red[0];
}

// ---------------- 2) finalize mean|w| ----------------
__global__ void k_wfin() {
    __shared__ float red[1024];
    int m = blockIdx.x;
    red[threadIdx.x] = g_part[m * 1024 + threadIdx.x];
    __syncthreads();
    for (int o = 512; o > 0; o >>= 1) {
        if (threadIdx.x < o) red[threadIdx.x] += red[threadIdx.x + o];
        __syncthreads();
    }
    if (threadIdx.x == 0) g_wnorm[m] = fmaxf(red[0] / (float)NW, 1e-5f);
}

// ---------------- 3) ternarize weights ----------------
__global__ void k_wquant(const float* __restrict__ w0, const float* __restrict__ w1,
                         const float* __restrict__ w2) {
    int m = blockIdx.y;
    const float* W = (m == 0) ? w0 : ((m == 1) ? w1 : w2);
    signed char* Q = (m == 0) ? g_wqg : ((m == 1) ? g_wqu : g_wqd);
    float ws = 1.0f / g_wnorm[m];
    int i4 = blockIdx.x * 256 + threadIdx.x;  // int4 (=16 int8) output index
    const float4* Wv = reinterpret_cast<const float4*>(W);
    int4 o;
    o.x = pack_q4(Wv[i4 * 4 + 0], ws, -1.f, 1.f);
    o.y = pack_q4(Wv[i4 * 4 + 1], ws, -1.f, 1.f);
    o.z = pack_q4(Wv[i4 * 4 + 2], ws, -1.f, 1.f);
    o.w = pack_q4(Wv[i4 * 4 + 3], ws, -1.f, 1.f);
    reinterpret_cast<int4*>(Q)[i4] = o;
}

// ---------------- 4) per-token act_quant of x ----------------
__global__ void k_actq1(const float* __restrict__ x) {
    __shared__ float red[256];
    int t = blockIdx.x;
    const float4* px = reinterpret_cast<const float4*>(x + (size_t)t * H_DIM);
    float4 v0 = px[threadIdx.x * 2], v1 = px[threadIdx.x * 2 + 1];
    float m = fmaxf(fmaxf(fmaxf(fabsf(v0.x), fabsf(v0.y)), fmaxf(fabsf(v0.z), fabsf(v0.w))),
                    fmaxf(fmaxf(fabsf(v1.x), fabsf(v1.y)), fmaxf(fabsf(v1.z), fabsf(v1.w))));
    red[threadIdx.x] = m;
    __syncthreads();
    for (int o = 128; o > 0; o >>= 1) {
        if (threadIdx.x < o) red[threadIdx.x] = fmaxf(red[threadIdx.x], red[threadIdx.x + o]);
        __syncthreads();
    }
    float scale = 128.f / fmaxf(red[0], 1e-5f);
    int p0 = pack_q4(v0, scale, -128.f, 127.f);
    int p1 = pack_q4(v1, scale, -128.f, 127.f);
    reinterpret_cast<int2*>(g_xq + (size_t)t * H_DIM)[threadIdx.x] = make_int2(p0, p1);
    if (threadIdx.x == 0) g_xs[t] = scale;
}

// ---------------- 5) GEMM1: gate+up fused, dp4a, SiLU epilogue ----------------
// C tile: 128 tokens x 64 outputs (both gate and up). K = 2048, BK = 64 bytes.
__global__ __launch_bounds__(256) void k_gemm1() {
    __shared__ int sA[16][128];
    __shared__ int sBg[16][64];
    __shared__ int sBu[16][64];
    const int tid = threadIdx.x;
    const int tx = tid & 15, ty = tid >> 4;
    const int row0 = ty * 8, col0 = tx * 4;
    const int m0 = blockIdx.y * 128, n0 = blockIdx.x * 64;

    int accg[8][4], accu[8][4];
#pragma unroll
    for (int i = 0; i < 8; i++)
#pragma unroll
        for (int j = 0; j < 4; j++) { accg[i][j] = 0; accu[i][j] = 0; }

    const int4* A4 = reinterpret_cast<const int4*>(g_xq + (size_t)m0 * H_DIM);
    const int4* G4 = reinterpret_cast<const int4*>(g_wqg + (size_t)n0 * H_DIM);
    const int4* U4 = reinterpret_cast<const int4*>(g_wqu + (size_t)n0 * H_DIM);
    // row stride in int4 units: H_DIM/16 = 128

    for (int kb = 0; kb < 32; kb++) {
        int kc = kb * 4;  // int4 offset along K
#pragma unroll
        for (int l = 0; l < 2; l++) {
            int idx = tid + l * 256;
            int r = idx >> 2, c = idx & 3;
            int4 v = A4[r * 128 + kc + c];
            sA[c * 4 + 0][r] = v.x; sA[c * 4 + 1][r] = v.y;
            sA[c * 4 + 2][r] = v.z; sA[c * 4 + 3][r] = v.w;
        }
        {
            int r = tid >> 2, c = tid & 3;
            int4 v = G4[r * 128 + kc + c];
            sBg[c * 4 + 0][r] = v.x; sBg[c * 4 + 1][r] = v.y;
            sBg[c * 4 + 2][r] = v.z; sBg[c * 4 + 3][r] = v.w;
            int4 u = U4[r * 128 + kc + c];
            sBu[c * 4 + 0][r] = u.x; sBu[c * 4 + 1][r] = u.y;
            sBu[c * 4 + 2][r] = u.z; sBu[c * 4 + 3][r] = u.w;
        }
        __syncthreads();
#pragma unroll
        for (int ki = 0; ki < 16; ki++) {
            int4 a0 = *reinterpret_cast<const int4*>(&sA[ki][row0]);
            int4 a1 = *reinterpret_cast<const int4*>(&sA[ki][row0 + 4]);
            int4 bg = *reinterpret_cast<const int4*>(&sBg[ki][col0]);
            int4 bu = *reinterpret_cast<const int4*>(&sBu[ki][col0]);
            int a[8] = {a0.x, a0.y, a0.z, a0.w, a1.x, a1.y, a1.z, a1.w};
            int gv[4] = {bg.x, bg.y, bg.z, bg.w};
            int uv[4] = {bu.x, bu.y, bu.z, bu.w};
#pragma unroll
            for (int i = 0; i < 8; i++) {
#pragma unroll
                for (int j = 0; j < 4; j++) {
                    accg[i][j] = __dp4a(a[i], gv[j], accg[i][j]);
                    accu[i][j] = __dp4a(a[i], uv[j], accu[i][j]);
                }
            }
        }
        __syncthreads();
    }
    float fg = g_wnorm[0], fu = g_wnorm[1];
#pragma unroll
    for (int i = 0; i < 8; i++) {
        int t = m0 + row0 + i;
        float inv = 1.0f / g_xs[t];
        float4 o;
        float* op = &o.x;
#pragma unroll
        for (int j = 0; j < 4; j++) {
            float gate = (float)accg[i][j] * fg * inv;
            float up   = (float)accu[i][j] * fu * inv;
            float sil  = gate / (1.0f + expf(-gate));
            op[j] = sil * up;
        }
        *reinterpret_cast<float4*>(&g_inter[(size_t)t * I_DIM + n0 + col0]) = o;
    }
}

// ---------------- 6) FWHT-8192 + act_quant #2 ----------------
__global__ __launch_bounds__(512) void k_fwht() {
    __shared__ float s[8192];
    __shared__ float red[512];
    const int tid = threadIdx.x;
    const int t = blockIdx.x;
    const float4* src = reinterpret_cast<const float4*>(g_inter + (size_t)t * I_DIM);
    float4* sv = reinterpret_cast<float4*>(s);
#pragma unroll
    for (int l = 0; l < 4; l++) sv[tid + l * 512] = src[tid + l * 512];
    __syncthreads();
    for (int h = 1; h < 8192; h <<= 1) {
#pragma unroll
        for (int l = 0; l < 8; l++) {
            int p = tid + l * 512;
            int i = ((p & ~(h - 1)) << 1) | (p & (h - 1));
            float a = s[i], b = s[i + h];
            s[i] = a + b;
            s[i + h] = a - b;
        }
        __syncthreads();
    }
    const float rn = 1.1048543456039805e-02f;  // 1/sqrt(8192)
    float m = 0.f;
#pragma unroll
    for (int l = 0; l < 16; l++) {
        int i = tid + l * 512;
        float v = s[i] * rn;
        s[i] = v;
        m = fmaxf(m, fabsf(v));
    }
    __syncthreads();
    red[tid] = m;
    __syncthreads();
    for (int o = 256; o > 0; o >>= 1) {
        if (tid < o) red[tid] = fmaxf(red[tid], red[tid + o]);
        __syncthreads();
    }
    float scale = 128.f / fmaxf(red[0], 1e-5f);
    int base = tid * 16;
    int w[4];
#pragma unroll
    for (int c = 0; c < 4; c++) {
        float4 v = *reinterpret_cast<float4*>(&s[base + c * 4]);
        w[c] = pack_q4(v, scale, -128.f, 127.f);
    }
    reinterpret_cast<int4*>(g_aq2 + (size_t)t * I_DIM)[tid] = make_int4(w[0], w[1], w[2], w[3]);
    if (tid == 0) g_as2[t] = scale;
}

// ---------------- 7) GEMM2: down projection, dp4a ----------------
// C tile: 128 tokens x 128 outputs. K = 8192, BK = 64 bytes.
__global__ __launch_bounds__(256) void k_gemm2(float* __restrict__ out) {
    __shared__ int sA[16][128];
    __shared__ int sB[16][128];
    const int tid = threadIdx.x;
    const int tx = tid & 15, ty = tid >> 4;
    const int row0 = ty * 8, col0 = tx * 8;
    const int m0 = blockIdx.y * 128, n0 = blockIdx.x * 128;

    int acc[8][8];
#pragma unroll
    for (int i = 0; i < 8; i++)
#pragma unroll
        for (int j = 0; j < 8; j++) acc[i][j] = 0;

    const int4* A4 = reinterpret_cast<const int4*>(g_aq2 + (size_t)m0 * I_DIM);
    const int4* B4 = reinterpret_cast<const int4*>(g_wqd + (size_t)n0 * I_DIM);
    // row stride in int4 units: I_DIM/16 = 512

    for (int kb = 0; kb < 128; kb++) {
        int kc = kb * 4;
#pragma unroll
        for (int l = 0; l < 2; l++) {
            int idx = tid + l * 256;
            int r = idx >> 2, c = idx & 3;
            int4 v = A4[(size_t)r * 512 + kc + c];
            sA[c * 4 + 0][r] = v.x; sA[c * 4 + 1][r] = v.y;
            sA[c * 4 + 2][r] = v.z; sA[c * 4 + 3][r] = v.w;
            int4 w = B4[(size_t)r * 512 + kc + c];
            sB[c * 4 + 0][r] = w.x; sB[c * 4 + 1][r] = w.y;
            sB[c * 4 + 2][r] = w.z; sB[c * 4 + 3][r] = w.w;
        }
        __syncthreads();
#pragma unroll
        for (int ki = 0; ki < 16; ki++) {
            int4 a0 = *reinterpret_cast<const int4*>(&sA[ki][row0]);
            int4 a1 = *reinterpret_cast<const int4*>(&sA[ki][row0 + 4]);
            int4 b0 = *reinterpret_cast<const int4*>(&sB[ki][col0]);
            int4 b1 = *reinterpret_cast<const int4*>(&sB[ki][col0 + 4]);
            int a[8] = {a0.x, a0.y, a0.z, a0.w, a1.x, a1.y, a1.z, a1.w};
            int b[8] = {b0.x, b0.y, b0.z, b0.w, b1.x, b1.y, b1.z, b1.w};
#pragma unroll
            for (int i = 0; i < 8; i++)
#pragma unroll
                for (int j = 0; j < 8; j++)
                    acc[i][j] = __dp4a(a[i], b[j], acc[i][j]);
        }
        __syncthreads();
    }
    float fw = g_wnorm[2];
#pragma unroll
    for (int i = 0; i < 8; i++) {
        int t = m0 + row0 + i;
        float f = fw / g_as2[t];
        float4 o0, o1;
        o0.x = acc[i][0] * f; o0.y = acc[i][1] * f; o0.z = acc[i][2] * f; o0.w = acc[i][3] * f;
        o1.x = acc[i][4] * f; o1.y = acc[i][5] * f; o1.z = acc[i][6] * f; o1.w = acc[i][7] * f;
        *reinterpret_cast<float4*>(&out[(size_t)t * H_DIM + n0 + col0]) = o0;
        *reinterpret_cast<float4*>(&out[(size_t)t * H_DIM + n0 + col0 + 4]) = o1;
    }
}

// ---------------- launch ----------------
extern "C" void kernel_launch(void* const* d_in, const int* in_sizes, int n_in,
                              void* d_out, int out_size) {
    const float* x  = (const float*)d_in[0];
    const float* wg = (const float*)d_in[1];
    const float* wu = (const float*)d_in[2];
    const float* wd = (const float*)d_in[3];
    float* out = (float*)d_out;

    k_wabs<<<dim3(1024, 3), 256>>>(wg, wu, wd);
    k_wfin<<<3, 1024>>>();
    k_wquant<<<dim3(4096, 3), 256>>>(wg, wu, wd);
    k_actq1<<<T_TOK, 256>>>(x);
    k_gemm1<<<dim3(I_DIM / 64, T_TOK / 128), 256>>>();
    k_fwht<<<T_TOK, 512>>>();
    k_gemm2<<<dim3(H_DIM / 128, T_TOK / 128), 256>>>(out);
}

// round 4
// speedup vs baseline: 3.7042x; 3.7042x over previous
#include <cuda_runtime.h>
#include <cuda_bf16.h>
#include <cstdint>

#define T_TOK 8192
#define H_DIM 2048
#define I_DIM 8192
#define NW    16777216

// ---------------- device scratch ----------------
__device__ float       g_part[3 * 1024];
__device__ float       g_wnorm[3];
__device__ signed char g_wqg[NW];
__device__ signed char g_wqu[NW];
__device__ signed char g_wqd[NW];
__device__ signed char g_xq[T_TOK * H_DIM];
__device__ float       g_xs[T_TOK];
__device__ float       g_inter[67108864];   // fp32 silu(gate)*up [T,I]
__device__ signed char g_aq2[67108864];     // int8 quantized fwht(inter)
__device__ float       g_as2[T_TOK];

// ---------------- helpers ----------------
__device__ __forceinline__ uint32_t smem_u32(const void* p) {
    uint32_t a;
    asm("{ .reg .u64 t; cvta.to.shared.u64 t, %1; cvt.u32.u64 %0, t; }" : "=r"(a) : "l"(p));
    return a;
}
#define CP_ASYNC16(dst, src) \
    asm volatile("cp.async.cg.shared.global [%0], [%1], 16;" :: "r"(dst), "l"(src) : "memory")
#define CP_COMMIT() asm volatile("cp.async.commit_group;" ::: "memory")
#define CP_WAIT(n)  asm volatile("cp.async.wait_group %0;" :: "n"(n) : "memory")

#define MMA_S8(C, A, B) \
    asm volatile("mma.sync.aligned.m16n8k32.row.col.s32.s8.s8.s32 " \
        "{%0,%1,%2,%3}, {%4,%5,%6,%7}, {%8,%9}, {%0,%1,%2,%3};" \
        : "+r"((C)[0]), "+r"((C)[1]), "+r"((C)[2]), "+r"((C)[3]) \
        : "r"((A)[0]), "r"((A)[1]), "r"((A)[2]), "r"((A)[3]), "r"((B)[0]), "r"((B)[1]))

__device__ __forceinline__ int pack_q4(float4 v, float s, float lo, float hi) {
    int q0 = (int)fminf(fmaxf(rintf(v.x * s), lo), hi);
    int q1 = (int)fminf(fmaxf(rintf(v.y * s), lo), hi);
    int q2 = (int)fminf(fmaxf(rintf(v.z * s), lo), hi);
    int q3 = (int)fminf(fmaxf(rintf(v.w * s), lo), hi);
    return (q0 & 0xff) | ((q1 & 0xff) << 8) | ((q2 & 0xff) << 16) | ((q3 & 0xff) << 24);
}

// ---------------- 1) |w| partial reduction ----------------
__global__ void k_wabs(const float* __restrict__ w0, const float* __restrict__ w1,
                       const float* __restrict__ w2) {
    __shared__ float red[256];
    const float* W = (blockIdx.y == 0) ? w0 : ((blockIdx.y == 1) ? w1 : w2);
    float s = 0.f;
    for (int idx = blockIdx.x * 256 + threadIdx.x; idx < NW / 4; idx += 1024 * 256) {
        float4 v = reinterpret_cast<const float4*>(W)[idx];
        s += fabsf(v.x) + fabsf(v.y) + fabsf(v.z) + fabsf(v.w);
    }
    red[threadIdx.x] = s;
    __syncthreads();
    for (int o = 128; o > 0; o >>= 1) {
        if (threadIdx.x < o) red[threadIdx.x] += red[threadIdx.x + o];
        __syncthreads();
    }
    if (threadIdx.x == 0) g_part[blockIdx.y * 1024 + blockIdx.x] = red[0];
}

// ---------------- 2) finalize mean|w| ----------------
__global__ void k_wfin() {
    __shared__ float red[1024];
    int m = blockIdx.x;
    red[threadIdx.x] = g_part[m * 1024 + threadIdx.x];
    __syncthreads();
    for (int o = 512; o > 0; o >>= 1) {
        if (threadIdx.x < o) red[threadIdx.x] += red[threadIdx.x + o];
        __syncthreads();
    }
    if (threadIdx.x == 0) g_wnorm[m] = fmaxf(red[0] / (float)NW, 1e-5f);
}

// ---------------- 3) ternarize weights ----------------
__global__ void k_wquant(const float* __restrict__ w0, const float* __restrict__ w1,
                         const float* __restrict__ w2) {
    int m = blockIdx.y;
    const float* W = (m == 0) ? w0 : ((m == 1) ? w1 : w2);
    signed char* Q = (m == 0) ? g_wqg : ((m == 1) ? g_wqu : g_wqd);
    float ws = 1.0f / g_wnorm[m];
    int i4 = blockIdx.x * 256 + threadIdx.x;
    const float4* Wv = reinterpret_cast<const float4*>(W);
    int4 o;
    o.x = pack_q4(Wv[i4 * 4 + 0], ws, -1.f, 1.f);
    o.y = pack_q4(Wv[i4 * 4 + 1], ws, -1.f, 1.f);
    o.z = pack_q4(Wv[i4 * 4 + 2], ws, -1.f, 1.f);
    o.w = pack_q4(Wv[i4 * 4 + 3], ws, -1.f, 1.f);
    reinterpret_cast<int4*>(Q)[i4] = o;
}

// ---------------- 4) per-token act_quant of x ----------------
__global__ void k_actq1(const float* __restrict__ x) {
    __shared__ float red[256];
    int t = blockIdx.x;
    const float4* px = reinterpret_cast<const float4*>(x + (size_t)t * H_DIM);
    float4 v0 = px[threadIdx.x * 2], v1 = px[threadIdx.x * 2 + 1];
    float m = fmaxf(fmaxf(fmaxf(fabsf(v0.x), fabsf(v0.y)), fmaxf(fabsf(v0.z), fabsf(v0.w))),
                    fmaxf(fmaxf(fabsf(v1.x), fabsf(v1.y)), fmaxf(fabsf(v1.z), fabsf(v1.w))));
    red[threadIdx.x] = m;
    __syncthreads();
    for (int o = 128; o > 0; o >>= 1) {
        if (threadIdx.x < o) red[threadIdx.x] = fmaxf(red[threadIdx.x], red[threadIdx.x + o]);
        __syncthreads();
    }
    float scale = 128.f / fmaxf(red[0], 1e-5f);
    int p0 = pack_q4(v0, scale, -128.f, 127.f);
    int p1 = pack_q4(v1, scale, -128.f, 127.f);
    reinterpret_cast<int2*>(g_xq + (size_t)t * H_DIM)[threadIdx.x] = make_int2(p0, p1);
    if (threadIdx.x == 0) g_xs[t] = scale;
}

// ---------------- 5) GEMM1: IMMA, gate+up interleaved, SiLU epilogue ----------------
// BM=128 tokens, 64 logical outputs (B tile = 128 interleaved rows: even=gate, odd=up).
// BK=64. 8 warps in 2(M) x 4(N); warp tile 64x32 smem-cols.
#define SSTRIDE 80
__global__ __launch_bounds__(256, 2) void k_gemm1() {
    __shared__ signed char sA[2][128 * SSTRIDE];
    __shared__ signed char sB[2][128 * SSTRIDE];
    const int tid = threadIdx.x, wid = tid >> 5, lane = tid & 31;
    const int gid = lane >> 2, tig = lane & 3;
    const int wm = wid >> 2, wn = wid & 3;
    const int m0 = blockIdx.y * 128, n0 = blockIdx.x * 64;
    const signed char* A = g_xq + (size_t)m0 * H_DIM;

    int c[4][4][4];
#pragma unroll
    for (int i = 0; i < 4; i++)
#pragma unroll
        for (int j = 0; j < 4; j++)
#pragma unroll
            for (int q = 0; q < 4; q++) c[i][j][q] = 0;

    auto load_stage = [&](int buf, int kb) {
        int koff = kb * 64;
#pragma unroll
        for (int l = 0; l < 2; l++) {
            int ch = tid + l * 256;      // 512 chunks of 16B
            int r = ch >> 2, c16 = ch & 3;
            CP_ASYNC16(smem_u32(&sA[buf][r * SSTRIDE + c16 * 16]),
                       A + (size_t)r * H_DIM + koff + c16 * 16);
            int n = n0 + (r >> 1);
            const signed char* W = (r & 1) ? g_wqu : g_wqg;
            CP_ASYNC16(smem_u32(&sB[buf][r * SSTRIDE + c16 * 16]),
                       W + (size_t)n * H_DIM + koff + c16 * 16);
        }
    };

    load_stage(0, 0);
    CP_COMMIT();
    int buf = 0;
    for (int kb = 0; kb < 32; kb++) {
        if (kb + 1 < 32) {
            load_stage(buf ^ 1, kb + 1);
            CP_COMMIT();
            CP_WAIT(1);
        } else {
            CP_WAIT(0);
        }
        __syncthreads();
        const signed char* As = sA[buf];
        const signed char* Bs = sB[buf];
#pragma unroll
        for (int ks = 0; ks < 2; ks++) {
            int a[4][4], b[4][2];
#pragma unroll
            for (int mi = 0; mi < 4; mi++) {
                const signed char* p = As + (wm * 64 + mi * 16 + gid) * SSTRIDE + ks * 32 + tig * 4;
                a[mi][0] = *reinterpret_cast<const int*>(p);
                a[mi][1] = *reinterpret_cast<const int*>(p + 8 * SSTRIDE);
                a[mi][2] = *reinterpret_cast<const int*>(p + 16);
                a[mi][3] = *reinterpret_cast<const int*>(p + 8 * SSTRIDE + 16);
            }
#pragma unroll
            for (int ni = 0; ni < 4; ni++) {
                const signed char* p = Bs + (wn * 32 + ni * 8 + gid) * SSTRIDE + ks * 32 + tig * 4;
                b[ni][0] = *reinterpret_cast<const int*>(p);
                b[ni][1] = *reinterpret_cast<const int*>(p + 16);
            }
#pragma unroll
            for (int mi = 0; mi < 4; mi++)
#pragma unroll
                for (int ni = 0; ni < 4; ni++) MMA_S8(c[mi][ni], a[mi], b[ni]);
        }
        __syncthreads();
        buf ^= 1;
    }

    float fg = g_wnorm[0], fu = g_wnorm[1];
#pragma unroll
    for (int mi = 0; mi < 4; mi++) {
        int t1 = m0 + wm * 64 + mi * 16 + gid, t2 = t1 + 8;
        float i1 = 1.0f / g_xs[t1], i2 = 1.0f / g_xs[t2];
#pragma unroll
        for (int ni = 0; ni < 4; ni++) {
            int n = n0 + wn * 16 + ni * 4 + tig;
            float gv1 = (float)c[mi][ni][0] * fg * i1;
            float uv1 = (float)c[mi][ni][1] * fu * i1;
            g_inter[(size_t)t1 * I_DIM + n] = gv1 / (1.0f + __expf(-gv1)) * uv1;
            float gv2 = (float)c[mi][ni][2] * fg * i2;
            float uv2 = (float)c[mi][ni][3] * fu * i2;
            g_inter[(size_t)t2 * I_DIM + n] = gv2 / (1.0f + __expf(-gv2)) * uv2;
        }
    }
}

// ---------------- 6) FWHT-8192 + act_quant #2 ----------------
__global__ __launch_bounds__(512) void k_fwht() {
    __shared__ float s[8192];
    __shared__ float red[512];
    const int tid = threadIdx.x;
    const int t = blockIdx.x;
    const float4* src = reinterpret_cast<const float4*>(g_inter + (size_t)t * I_DIM);
    float v[16];
    float4* vv = reinterpret_cast<float4*>(v);
#pragma unroll
    for (int i = 0; i < 4; i++) vv[i] = src[tid * 4 + i];
    // 4 register stages (h = 1,2,4,8), same butterfly order as reference
#pragma unroll
    for (int h = 1; h < 16; h <<= 1) {
#pragma unroll
        for (int i = 0; i < 16; i++) {
            if ((i & h) == 0) {
                float a = v[i], b = v[i + h];
                v[i] = a + b;
                v[i + h] = a - b;
            }
        }
    }
#pragma unroll
    for (int i = 0; i < 4; i++) reinterpret_cast<float4*>(s)[tid * 4 + i] = vv[i];
    __syncthreads();
    for (int h = 16; h < 8192; h <<= 1) {
#pragma unroll
        for (int l = 0; l < 8; l++) {
            int p = tid + l * 512;
            int i = ((p & ~(h - 1)) << 1) | (p & (h - 1));
            float a = s[i], b = s[i + h];
            s[i] = a + b;
            s[i + h] = a - b;
        }
        __syncthreads();
    }
    const float rn = 1.1048543456039805e-02f;  // 1/sqrt(8192)
    float m = 0.f;
#pragma unroll
    for (int i = 0; i < 4; i++) {
        float4 w = reinterpret_cast<float4*>(s)[tid * 4 + i];
        w.x *= rn; w.y *= rn; w.z *= rn; w.w *= rn;
        vv[i] = w;
        m = fmaxf(m, fmaxf(fmaxf(fabsf(w.x), fabsf(w.y)), fmaxf(fabsf(w.z), fabsf(w.w))));
    }
    red[tid] = m;
    __syncthreads();
    for (int o = 256; o > 0; o >>= 1) {
        if (tid < o) red[tid] = fmaxf(red[tid], red[tid + o]);
        __syncthreads();
    }
    float scale = 128.f / fmaxf(red[0], 1e-5f);
    int w0 = pack_q4(vv[0], scale, -128.f, 127.f);
    int w1 = pack_q4(vv[1], scale, -128.f, 127.f);
    int w2 = pack_q4(vv[2], scale, -128.f, 127.f);
    int w3 = pack_q4(vv[3], scale, -128.f, 127.f);
    reinterpret_cast<int4*>(g_aq2 + (size_t)t * I_DIM)[tid] = make_int4(w0, w1, w2, w3);
    if (tid == 0) g_as2[t] = scale;
}

// ---------------- 7) GEMM2: IMMA down projection ----------------
// BM=128, BN=128, BK=64; 8 warps 2x4; warp tile 64x32.
__global__ __launch_bounds__(256, 2) void k_gemm2(float* __restrict__ out) {
    __shared__ signed char sA[2][128 * SSTRIDE];
    __shared__ signed char sB[2][128 * SSTRIDE];
    const int tid = threadIdx.x, wid = tid >> 5, lane = tid & 31;
    const int gid = lane >> 2, tig = lane & 3;
    const int wm = wid >> 2, wn = wid & 3;
    const int m0 = blockIdx.y * 128, n0 = blockIdx.x * 128;
    const signed char* A = g_aq2 + (size_t)m0 * I_DIM;
    const signed char* B = g_wqd + (size_t)n0 * I_DIM;

    int c[4][4][4];
#pragma unroll
    for (int i = 0; i < 4; i++)
#pragma unroll
        for (int j = 0; j < 4; j++)
#pragma unroll
            for (int q = 0; q < 4; q++) c[i][j][q] = 0;

    auto load_stage = [&](int buf, int kb) {
        int koff = kb * 64;
#pragma unroll
        for (int l = 0; l < 2; l++) {
            int ch = tid + l * 256;
            int r = ch >> 2, c16 = ch & 3;
            CP_ASYNC16(smem_u32(&sA[buf][r * SSTRIDE + c16 * 16]),
                       A + (size_t)r * I_DIM + koff + c16 * 16);
            CP_ASYNC16(smem_u32(&sB[buf][r * SSTRIDE + c16 * 16]),
                       B + (size_t)r * I_DIM + koff + c16 * 16);
        }
    };

    load_stage(0, 0);
    CP_COMMIT();
    int buf = 0;
    for (int kb = 0; kb < 128; kb++) {
        if (kb + 1 < 128) {
            load_stage(buf ^ 1, kb + 1);
            CP_COMMIT();
            CP_WAIT(1);
        } else {
            CP_WAIT(0);
        }
        __syncthreads();
        const signed char* As = sA[buf];
        const signed char* Bs = sB[buf];
#pragma unroll
        for (int ks = 0; ks < 2; ks++) {
            int a[4][4], b[4][2];
#pragma unroll
            for (int mi = 0; mi < 4; mi++) {
                const signed char* p = As + (wm * 64 + mi * 16 + gid) * SSTRIDE + ks * 32 + tig * 4;
                a[mi][0] = *reinterpret_cast<const int*>(p);
                a[mi][1] = *reinterpret_cast<const int*>(p + 8 * SSTRIDE);
                a[mi][2] = *reinterpret_cast<const int*>(p + 16);
                a[mi][3] = *reinterpret_cast<const int*>(p + 8 * SSTRIDE + 16);
            }
#pragma unroll
            for (int ni = 0; ni < 4; ni++) {
                const signed char* p = Bs + (wn * 32 + ni * 8 + gid) * SSTRIDE + ks * 32 + tig * 4;
                b[ni][0] = *reinterpret_cast<const int*>(p);
                b[ni][1] = *reinterpret_cast<const int*>(p + 16);
            }
#pragma unroll
            for (int mi = 0; mi < 4; mi++)
#pragma unroll
                for (int ni = 0; ni < 4; ni++) MMA_S8(c[mi][ni], a[mi], b[ni]);
        }
        __syncthreads();
        buf ^= 1;
    }

    float fw = g_wnorm[2];
#pragma unroll
    for (int mi = 0; mi < 4; mi++) {
        int t1 = m0 + wm * 64 + mi * 16 + gid, t2 = t1 + 8;
        float f1 = fw / g_as2[t1], f2 = fw / g_as2[t2];
#pragma unroll
        for (int ni = 0; ni < 4; ni++) {
            int col = n0 + wn * 32 + ni * 8 + tig * 2;
            float2 o1 = make_float2((float)c[mi][ni][0] * f1, (float)c[mi][ni][1] * f1);
            float2 o2 = make_float2((float)c[mi][ni][2] * f2, (float)c[mi][ni][3] * f2);
            *reinterpret_cast<float2*>(&out[(size_t)t1 * H_DIM + col]) = o1;
            *reinterpret_cast<float2*>(&out[(size_t)t2 * H_DIM + col]) = o2;
        }
    }
}

// ---------------- launch ----------------
extern "C" void kernel_launch(void* const* d_in, const int* in_sizes, int n_in,
                              void* d_out, int out_size) {
    const float* x  = (const float*)d_in[0];
    const float* wg = (const float*)d_in[1];
    const float* wu = (const float*)d_in[2];
    const float* wd = (const float*)d_in[3];
    float* out = (float*)d_out;

    k_wabs<<<dim3(1024, 3), 256>>>(wg, wu, wd);
    k_wfin<<<3, 1024>>>();
    k_wquant<<<dim3(4096, 3), 256>>>(wg, wu, wd);
    k_actq1<<<T_TOK, 256>>>(x);
    k_gemm1<<<dim3(I_DIM / 64, T_TOK / 128), 256>>>();
    k_fwht<<<T_TOK, 512>>>();
    k_gemm2<<<dim3(H_DIM / 128, T_TOK / 128), 256>>>(out);
}

// round 5
// speedup vs baseline: 4.0245x; 1.0865x over previous
#include <cuda_runtime.h>
#include <cuda_bf16.h>
#include <cstdint>

#define T_TOK 8192
#define H_DIM 2048
#define I_DIM 8192
#define NW    16777216

// ---------------- device scratch ----------------
__device__ float       g_part[3 * 1024];
__device__ float       g_wnorm[3];
__device__ signed char g_wqg[NW];
__device__ signed char g_wqu[NW];
__device__ signed char g_wqd[NW];
__device__ signed char g_xq[T_TOK * H_DIM];
__device__ float       g_xs[T_TOK];
__device__ float       g_inter[67108864];   // fp32 silu(gate)*up [T,I]
__device__ signed char g_aq2[67108864];     // int8 quantized fwht(inter)
__device__ float       g_as2[T_TOK];

// ---------------- helpers ----------------
__device__ __forceinline__ uint32_t smem_u32(const void* p) {
    uint32_t a;
    asm("{ .reg .u64 t; cvta.to.shared.u64 t, %1; cvt.u32.u64 %0, t; }" : "=r"(a) : "l"(p));
    return a;
}
#define CP_ASYNC16(dst, src) \
    asm volatile("cp.async.cg.shared.global [%0], [%1], 16;" :: "r"(dst), "l"(src) : "memory")
#define CP_COMMIT() asm volatile("cp.async.commit_group;" ::: "memory")
#define CP_WAIT(n)  asm volatile("cp.async.wait_group %0;" :: "n"(n) : "memory")

#define MMA_S8(C, A, B) \
    asm volatile("mma.sync.aligned.m16n8k32.row.col.s32.s8.s8.s32 " \
        "{%0,%1,%2,%3}, {%4,%5,%6,%7}, {%8,%9}, {%0,%1,%2,%3};" \
        : "+r"((C)[0]), "+r"((C)[1]), "+r"((C)[2]), "+r"((C)[3]) \
        : "r"((A)[0]), "r"((A)[1]), "r"((A)[2]), "r"((A)[3]), "r"((B)[0]), "r"((B)[1]))

__device__ __forceinline__ int pack_q4(float4 v, float s, float lo, float hi) {
    int q0 = (int)fminf(fmaxf(rintf(v.x * s), lo), hi);
    int q1 = (int)fminf(fmaxf(rintf(v.y * s), lo), hi);
    int q2 = (int)fminf(fmaxf(rintf(v.z * s), lo), hi);
    int q3 = (int)fminf(fmaxf(rintf(v.w * s), lo), hi);
    return (q0 & 0xff) | ((q1 & 0xff) << 8) | ((q2 & 0xff) << 16) | ((q3 & 0xff) << 24);
}

// ---------------- 1) |w| partial reduction ----------------
__global__ void k_wabs(const float* __restrict__ w0, const float* __restrict__ w1,
                       const float* __restrict__ w2) {
    __shared__ float red[256];
    const float* W = (blockIdx.y == 0) ? w0 : ((blockIdx.y == 1) ? w1 : w2);
    float s = 0.f;
    for (int idx = blockIdx.x * 256 + threadIdx.x; idx < NW / 4; idx += 1024 * 256) {
        float4 v = reinterpret_cast<const float4*>(W)[idx];
        s += fabsf(v.x) + fabsf(v.y) + fabsf(v.z) + fabsf(v.w);
    }
    red[threadIdx.x] = s;
    __syncthreads();
    for (int o = 128; o > 0; o >>= 1) {
        if (threadIdx.x < o) red[threadIdx.x] += red[threadIdx.x + o];
        __syncthreads();
    }
    if (threadIdx.x == 0) g_part[blockIdx.y * 1024 + blockIdx.x] = red[0];
}

// ---------------- 2) finalize mean|w| ----------------
__global__ void k_wfin() {
    __shared__ float red[1024];
    int m = blockIdx.x;
    red[threadIdx.x] = g_part[m * 1024 + threadIdx.x];
    __syncthreads();
    for (int o = 512; o > 0; o >>= 1) {
        if (threadIdx.x < o) red[threadIdx.x] += red[threadIdx.x + o];
        __syncthreads();
    }
    if (threadIdx.x == 0) g_wnorm[m] = fmaxf(red[0] / (float)NW, 1e-5f);
}

// ---------------- 3) ternarize weights ----------------
__global__ void k_wquant(const float* __restrict__ w0, const float* __restrict__ w1,
                         const float* __restrict__ w2) {
    int m = blockIdx.y;
    const float* W = (m == 0) ? w0 : ((m == 1) ? w1 : w2);
    signed char* Q = (m == 0) ? g_wqg : ((m == 1) ? g_wqu : g_wqd);
    float ws = 1.0f / g_wnorm[m];
    int i4 = blockIdx.x * 256 + threadIdx.x;
    const float4* Wv = reinterpret_cast<const float4*>(W);
    int4 o;
    o.x = pack_q4(Wv[i4 * 4 + 0], ws, -1.f, 1.f);
    o.y = pack_q4(Wv[i4 * 4 + 1], ws, -1.f, 1.f);
    o.z = pack_q4(Wv[i4 * 4 + 2], ws, -1.f, 1.f);
    o.w = pack_q4(Wv[i4 * 4 + 3], ws, -1.f, 1.f);
    reinterpret_cast<int4*>(Q)[i4] = o;
}

// ---------------- 4) per-token act_quant of x ----------------
__global__ void k_actq1(const float* __restrict__ x) {
    __shared__ float red[256];
    int t = blockIdx.x;
    const float4* px = reinterpret_cast<const float4*>(x + (size_t)t * H_DIM);
    float4 v0 = px[threadIdx.x * 2], v1 = px[threadIdx.x * 2 + 1];
    float m = fmaxf(fmaxf(fmaxf(fabsf(v0.x), fabsf(v0.y)), fmaxf(fabsf(v0.z), fabsf(v0.w))),
                    fmaxf(fmaxf(fabsf(v1.x), fabsf(v1.y)), fmaxf(fabsf(v1.z), fabsf(v1.w))));
    red[threadIdx.x] = m;
    __syncthreads();
    for (int o = 128; o > 0; o >>= 1) {
        if (threadIdx.x < o) red[threadIdx.x] = fmaxf(red[threadIdx.x], red[threadIdx.x + o]);
        __syncthreads();
    }
    float scale = 128.f / fmaxf(red[0], 1e-5f);
    int p0 = pack_q4(v0, scale, -128.f, 127.f);
    int p1 = pack_q4(v1, scale, -128.f, 127.f);
    reinterpret_cast<int2*>(g_xq + (size_t)t * H_DIM)[threadIdx.x] = make_int2(p0, p1);
    if (threadIdx.x == 0) g_xs[t] = scale;
}

// ---------------- GEMM common geometry ----------------
// BM=128, 128 B-rows, BK=64, 8 warps 2(M)x4(N), warp tile 64x32, 3-stage cp.async.
#define SSTRIDE 80
#define STG_SZ  (128 * SSTRIDE)   // 10240 B per operand per stage
#define DSMEM   (6 * STG_SZ)      // 3 stages x (A+B) = 61440 B

// ---------------- 5) GEMM1: IMMA, gate+up interleaved, SiLU epilogue ----------------
__global__ __launch_bounds__(256, 2) void k_gemm1() {
    extern __shared__ signed char dyn[];
    const int tid = threadIdx.x, wid = tid >> 5, lane = tid & 31;
    const int gid = lane >> 2, tig = lane & 3;
    const int wm = wid >> 2, wn = wid & 3;
    const int m0 = blockIdx.y * 128, n0 = blockIdx.x * 64;
    const signed char* A = g_xq + (size_t)m0 * H_DIM;

    int c[4][4][4];
#pragma unroll
    for (int i = 0; i < 4; i++)
#pragma unroll
        for (int j = 0; j < 4; j++)
#pragma unroll
            for (int q = 0; q < 4; q++) c[i][j][q] = 0;

    auto load_stage = [&](int st, int kb) {
        int koff = kb * 64;
        signed char* dA = dyn + st * STG_SZ;
        signed char* dB = dyn + 3 * STG_SZ + st * STG_SZ;
#pragma unroll
        for (int l = 0; l < 2; l++) {
            int ch = tid + l * 256;
            int r = ch >> 2, c16 = ch & 3;
            CP_ASYNC16(smem_u32(&dA[r * SSTRIDE + c16 * 16]),
                       A + (size_t)r * H_DIM + koff + c16 * 16);
            int n = n0 + (r >> 1);
            const signed char* W = (r & 1) ? g_wqu : g_wqg;
            CP_ASYNC16(smem_u32(&dB[r * SSTRIDE + c16 * 16]),
                       W + (size_t)n * H_DIM + koff + c16 * 16);
        }
    };

    load_stage(0, 0); CP_COMMIT();
    load_stage(1, 1); CP_COMMIT();

    const int NKB = 32;
    for (int kb = 0; kb < NKB; kb++) {
        if (kb == NKB - 1) { CP_WAIT(0); } else { CP_WAIT(1); }
        __syncthreads();
        if (kb + 2 < NKB) { load_stage((kb + 2) % 3, kb + 2); CP_COMMIT(); }
        int st = kb % 3;
        const signed char* As = dyn + st * STG_SZ;
        const signed char* Bs = dyn + 3 * STG_SZ + st * STG_SZ;
#pragma unroll
        for (int ks = 0; ks < 2; ks++) {
            int a[4][4], b[4][2];
#pragma unroll
            for (int mi = 0; mi < 4; mi++) {
                const signed char* p = As + (wm * 64 + mi * 16 + gid) * SSTRIDE + ks * 32 + tig * 4;
                a[mi][0] = *reinterpret_cast<const int*>(p);
                a[mi][1] = *reinterpret_cast<const int*>(p + 8 * SSTRIDE);
                a[mi][2] = *reinterpret_cast<const int*>(p + 16);
                a[mi][3] = *reinterpret_cast<const int*>(p + 8 * SSTRIDE + 16);
            }
#pragma unroll
            for (int ni = 0; ni < 4; ni++) {
                const signed char* p = Bs + (wn * 32 + ni * 8 + gid) * SSTRIDE + ks * 32 + tig * 4;
                b[ni][0] = *reinterpret_cast<const int*>(p);
                b[ni][1] = *reinterpret_cast<const int*>(p + 16);
            }
#pragma unroll
            for (int mi = 0; mi < 4; mi++)
#pragma unroll
                for (int ni = 0; ni < 4; ni++) MMA_S8(c[mi][ni], a[mi], b[ni]);
        }
    }

    float fg = g_wnorm[0], fu = g_wnorm[1];
#pragma unroll
    for (int mi = 0; mi < 4; mi++) {
        int t1 = m0 + wm * 64 + mi * 16 + gid, t2 = t1 + 8;
        float i1 = 1.0f / g_xs[t1], i2 = 1.0f / g_xs[t2];
#pragma unroll
        for (int ni = 0; ni < 4; ni++) {
            int n = n0 + wn * 16 + ni * 4 + tig;
            float gv1 = (float)c[mi][ni][0] * fg * i1;
            float uv1 = (float)c[mi][ni][1] * fu * i1;
            g_inter[(size_t)t1 * I_DIM + n] = gv1 / (1.0f + __expf(-gv1)) * uv1;
            float gv2 = (float)c[mi][ni][2] * fg * i2;
            float uv2 = (float)c[mi][ni][3] * fu * i2;
            g_inter[(size_t)t2 * I_DIM + n] = gv2 / (1.0f + __expf(-gv2)) * uv2;
        }
    }
}

// ---------------- 6) FWHT-8192 + act_quant #2 (register-chunked) ----------------
__global__ __launch_bounds__(512) void k_fwht() {
    __shared__ float s[8192];
    __shared__ float red[512];
    const int tid = threadIdx.x;
    const int t = blockIdx.x;
    float v[16];
    float4* vv = reinterpret_cast<float4*>(v);

    // chunk 1: contiguous 16 elements, stages h = 1,2,4,8
    const float4* src = reinterpret_cast<const float4*>(g_inter + (size_t)t * I_DIM);
#pragma unroll
    for (int i = 0; i < 4; i++) vv[i] = src[tid * 4 + i];
#pragma unroll
    for (int h = 1; h < 16; h <<= 1)
#pragma unroll
        for (int i = 0; i < 16; i++)
            if ((i & h) == 0) {
                float a = v[i], b = v[i + h];
                v[i] = a + b; v[i + h] = a - b;
            }
#pragma unroll
    for (int i = 0; i < 4; i++) reinterpret_cast<float4*>(s)[tid * 4 + i] = vv[i];
    __syncthreads();

    // chunk 2: stride-16 gather, stages h = 16,32,64,128
    int b2 = (tid & 15) + ((tid >> 4) << 8);
#pragma unroll
    for (int j = 0; j < 16; j++) v[j] = s[b2 + 16 * j];
#pragma unroll
    for (int h = 1; h < 16; h <<= 1)
#pragma unroll
        for (int j = 0; j < 16; j++)
            if ((j & h) == 0) {
                float a = v[j], b = v[j + h];
                v[j] = a + b; v[j + h] = a - b;
            }
#pragma unroll
    for (int j = 0; j < 16; j++) s[b2 + 16 * j] = v[j];
    __syncthreads();

    // chunk 3: stride-256 gather, stages h = 256,512,1024,2048
    int b3 = (tid & 255) + ((tid >> 8) << 12);
#pragma unroll
    for (int j = 0; j < 16; j++) v[j] = s[b3 + 256 * j];
#pragma unroll
    for (int h = 1; h < 16; h <<= 1)
#pragma unroll
        for (int j = 0; j < 16; j++)
            if ((j & h) == 0) {
                float a = v[j], b = v[j + h];
                v[j] = a + b; v[j + h] = a - b;
            }
#pragma unroll
    for (int j = 0; j < 16; j++) s[b3 + 256 * j] = v[j];
    __syncthreads();

    // final stage h = 4096 + normalize + max + quantize
    const float rn = 1.1048543456039805e-02f;  // 1/sqrt(8192)
    float lo[8], hi[8];
    float m = 0.f;
#pragma unroll
    for (int q = 0; q < 8; q++) {
        float a = s[tid * 8 + q], b = s[tid * 8 + q + 4096];
        float na = (a + b) * rn, nb = (a - b) * rn;
        lo[q] = na; hi[q] = nb;
        m = fmaxf(m, fmaxf(fabsf(na), fabsf(nb)));
    }
    red[tid] = m;
    __syncthreads();
    for (int o = 256; o > 0; o >>= 1) {
        if (tid < o) red[tid] = fmaxf(red[tid], red[tid + o]);
        __syncthreads();
    }
    float scale = 128.f / fmaxf(red[0], 1e-5f);
    float4* lv = reinterpret_cast<float4*>(lo);
    float4* hv = reinterpret_cast<float4*>(hi);
    int2 plo = make_int2(pack_q4(lv[0], scale, -128.f, 127.f),
                         pack_q4(lv[1], scale, -128.f, 127.f));
    int2 phi = make_int2(pack_q4(hv[0], scale, -128.f, 127.f),
                         pack_q4(hv[1], scale, -128.f, 127.f));
    int2* orow = reinterpret_cast<int2*>(g_aq2 + (size_t)t * I_DIM);
    orow[tid] = plo;
    orow[tid + 512] = phi;
    if (tid == 0) g_as2[t] = scale;
}

// ---------------- 7) GEMM2: IMMA down projection ----------------
__global__ __launch_bounds__(256, 2) void k_gemm2(float* __restrict__ out) {
    extern __shared__ signed char dyn[];
    const int tid = threadIdx.x, wid = tid >> 5, lane = tid & 31;
    const int gid = lane >> 2, tig = lane & 3;
    const int wm = wid >> 2, wn = wid & 3;
    const int m0 = blockIdx.y * 128, n0 = blockIdx.x * 128;
    const signed char* A = g_aq2 + (size_t)m0 * I_DIM;
    const signed char* B = g_wqd + (size_t)n0 * I_DIM;

    int c[4][4][4];
#pragma unroll
    for (int i = 0; i < 4; i++)
#pragma unroll
        for (int j = 0; j < 4; j++)
#pragma unroll
            for (int q = 0; q < 4; q++) c[i][j][q] = 0;

    auto load_stage = [&](int st, int kb) {
        int koff = kb * 64;
        signed char* dA = dyn + st * STG_SZ;
        signed char* dB = dyn + 3 * STG_SZ + st * STG_SZ;
#pragma unroll
        for (int l = 0; l < 2; l++) {
            int ch = tid + l * 256;
            int r = ch >> 2, c16 = ch & 3;
            CP_ASYNC16(smem_u32(&dA[r * SSTRIDE + c16 * 16]),
                       A + (size_t)r * I_DIM + koff + c16 * 16);
            CP_ASYNC16(smem_u32(&dB[r * SSTRIDE + c16 * 16]),
                       B + (size_t)r * I_DIM + koff + c16 * 16);
        }
    };

    load_stage(0, 0); CP_COMMIT();
    load_stage(1, 1); CP_COMMIT();

    const int NKB = 128;
    for (int kb = 0; kb < NKB; kb++) {
        if (kb == NKB - 1) { CP_WAIT(0); } else { CP_WAIT(1); }
        __syncthreads();
        if (kb + 2 < NKB) { load_stage((kb + 2) % 3, kb + 2); CP_COMMIT(); }
        int st = kb % 3;
        const signed char* As = dyn + st * STG_SZ;
        const signed char* Bs = dyn + 3 * STG_SZ + st * STG_SZ;
#pragma unroll
        for (int ks = 0; ks < 2; ks++) {
            int a[4][4], b[4][2];
#pragma unroll
            for (int mi = 0; mi < 4; mi++) {
                const signed char* p = As + (wm * 64 + mi * 16 + gid) * SSTRIDE + ks * 32 + tig * 4;
                a[mi][0] = *reinterpret_cast<const int*>(p);
                a[mi][1] = *reinterpret_cast<const int*>(p + 8 * SSTRIDE);
                a[mi][2] = *reinterpret_cast<const int*>(p + 16);
                a[mi][3] = *reinterpret_cast<const int*>(p + 8 * SSTRIDE + 16);
            }
#pragma unroll
            for (int ni = 0; ni < 4; ni++) {
                const signed char* p = Bs + (wn * 32 + ni * 8 + gid) * SSTRIDE + ks * 32 + tig * 4;
                b[ni][0] = *reinterpret_cast<const int*>(p);
                b[ni][1] = *reinterpret_cast<const int*>(p + 16);
            }
#pragma unroll
            for (int mi = 0; mi < 4; mi++)
#pragma unroll
                for (int ni = 0; ni < 4; ni++) MMA_S8(c[mi][ni], a[mi], b[ni]);
        }
    }

    float fw = g_wnorm[2];
#pragma unroll
    for (int mi = 0; mi < 4; mi++) {
        int t1 = m0 + wm * 64 + mi * 16 + gid, t2 = t1 + 8;
        float f1 = fw / g_as2[t1], f2 = fw / g_as2[t2];
#pragma unroll
        for (int ni = 0; ni < 4; ni++) {
            int col = n0 + wn * 32 + ni * 8 + tig * 2;
            float2 o1 = make_float2((float)c[mi][ni][0] * f1, (float)c[mi][ni][1] * f1);
            float2 o2 = make_float2((float)c[mi][ni][2] * f2, (float)c[mi][ni][3] * f2);
            *reinterpret_cast<float2*>(&out[(size_t)t1 * H_DIM + col]) = o1;
            *reinterpret_cast<float2*>(&out[(size_t)t2 * H_DIM + col]) = o2;
        }
    }
}

// ---------------- launch ----------------
extern "C" void kernel_launch(void* const* d_in, const int* in_sizes, int n_in,
                              void* d_out, int out_size) {
    const float* x  = (const float*)d_in[0];
    const float* wg = (const float*)d_in[1];
    const float* wu = (const float*)d_in[2];
    const float* wd = (const float*)d_in[3];
    float* out = (float*)d_out;

    static int configured = 0;
    if (!configured) {
        cudaFuncSetAttribute(k_gemm1, cudaFuncAttributeMaxDynamicSharedMemorySize, DSMEM);
        cudaFuncSetAttribute(k_gemm2, cudaFuncAttributeMaxDynamicSharedMemorySize, DSMEM);
        configured = 1;
    }

    k_wabs<<<dim3(1024, 3), 256>>>(wg, wu, wd);
    k_wfin<<<3, 1024>>>();
    k_wquant<<<dim3(4096, 3), 256>>>(wg, wu, wd);
    k_actq1<<<T_TOK, 256>>>(x);
    k_gemm1<<<dim3(I_DIM / 64, T_TOK / 128), 256, DSMEM>>>();
    k_fwht<<<T_TOK, 512>>>();
    k_gemm2<<<dim3(H_DIM / 128, T_TOK / 128), 256, DSMEM>>>(out);
}

// round 6
// speedup vs baseline: 4.3470x; 1.0801x over previous
#include <cuda_runtime.h>
#include <cuda_bf16.h>
#include <cstdint>

#define T_TOK 8192
#define H_DIM 2048
#define I_DIM 8192
#define NW    16777216

// ---------------- device scratch ----------------
__device__ float       g_part[3 * 1024];
__device__ float       g_wnorm[3];
__device__ signed char g_wqg[NW];
__device__ signed char g_wqu[NW];
__device__ signed char g_wqd[NW];
__device__ signed char g_xq[T_TOK * H_DIM];
__device__ float       g_xs[T_TOK];
__device__ float       g_inter[67108864];   // fp32 silu(gate)*up [T,I]
__device__ signed char g_aq2[67108864];     // int8 quantized fwht(inter)
__device__ float       g_as2[T_TOK];

// ---------------- helpers ----------------
__device__ __forceinline__ uint32_t smem_u32(const void* p) {
    uint32_t a;
    asm("{ .reg .u64 t; cvta.to.shared.u64 t, %1; cvt.u32.u64 %0, t; }" : "=r"(a) : "l"(p));
    return a;
}
#define CP_ASYNC16(dst, src) \
    asm volatile("cp.async.cg.shared.global [%0], [%1], 16;" :: "r"(dst), "l"(src) : "memory")
#define CP_COMMIT() asm volatile("cp.async.commit_group;" ::: "memory")
#define CP_WAIT(n)  asm volatile("cp.async.wait_group %0;" :: "n"(n) : "memory")

#define MMA_S8(C, A, B) \
    asm volatile("mma.sync.aligned.m16n8k32.row.col.s32.s8.s8.s32 " \
        "{%0,%1,%2,%3}, {%4,%5,%6,%7}, {%8,%9}, {%0,%1,%2,%3};" \
        : "+r"((C)[0]), "+r"((C)[1]), "+r"((C)[2]), "+r"((C)[3]) \
        : "r"((A)[0]), "r"((A)[1]), "r"((A)[2]), "r"((A)[3]), "r"((B)[0]), "r"((B)[1]))

#define LDSM_X4(R0, R1, R2, R3, addr) \
    asm volatile("ldmatrix.sync.aligned.m8n8.x4.shared.b16 {%0,%1,%2,%3}, [%4];" \
        : "=r"(R0), "=r"(R1), "=r"(R2), "=r"(R3) : "r"(addr))

__device__ __forceinline__ int pack_q4(float4 v, float s, float lo, float hi) {
    int q0 = (int)fminf(fmaxf(rintf(v.x * s), lo), hi);
    int q1 = (int)fminf(fmaxf(rintf(v.y * s), lo), hi);
    int q2 = (int)fminf(fmaxf(rintf(v.z * s), lo), hi);
    int q3 = (int)fminf(fmaxf(rintf(v.w * s), lo), hi);
    return (q0 & 0xff) | ((q1 & 0xff) << 8) | ((q2 & 0xff) << 16) | ((q3 & 0xff) << 24);
}

// ---------------- 1) |w| partial reduction ----------------
__global__ void k_wabs(const float* __restrict__ w0, const float* __restrict__ w1,
                       const float* __restrict__ w2) {
    __shared__ float red[256];
    const float* W = (blockIdx.y == 0) ? w0 : ((blockIdx.y == 1) ? w1 : w2);
    float s = 0.f;
    for (int idx = blockIdx.x * 256 + threadIdx.x; idx < NW / 4; idx += 1024 * 256) {
        float4 v = reinterpret_cast<const float4*>(W)[idx];
        s += fabsf(v.x) + fabsf(v.y) + fabsf(v.z) + fabsf(v.w);
    }
    red[threadIdx.x] = s;
    __syncthreads();
    for (int o = 128; o > 0; o >>= 1) {
        if (threadIdx.x < o) red[threadIdx.x] += red[threadIdx.x + o];
        __syncthreads();
    }
    if (threadIdx.x == 0) g_part[blockIdx.y * 1024 + blockIdx.x] = red[0];
}

// ---------------- 2) finalize mean|w| ----------------
__global__ void k_wfin() {
    __shared__ float red[1024];
    int m = blockIdx.x;
    red[threadIdx.x] = g_part[m * 1024 + threadIdx.x];
    __syncthreads();
    for (int o = 512; o > 0; o >>= 1) {
        if (threadIdx.x < o) red[threadIdx.x] += red[threadIdx.x + o];
        __syncthreads();
    }
    if (threadIdx.x == 0) g_wnorm[m] = fmaxf(red[0] / (float)NW, 1e-5f);
}

// ---------------- 3) ternarize weights ----------------
__global__ void k_wquant(const float* __restrict__ w0, const float* __restrict__ w1,
                         const float* __restrict__ w2) {
    int m = blockIdx.y;
    const float* W = (m == 0) ? w0 : ((m == 1) ? w1 : w2);
    signed char* Q = (m == 0) ? g_wqg : ((m == 1) ? g_wqu : g_wqd);
    float ws = 1.0f / g_wnorm[m];
    int i4 = blockIdx.x * 256 + threadIdx.x;
    const float4* Wv = reinterpret_cast<const float4*>(W);
    int4 o;
    o.x = pack_q4(Wv[i4 * 4 + 0], ws, -1.f, 1.f);
    o.y = pack_q4(Wv[i4 * 4 + 1], ws, -1.f, 1.f);
    o.z = pack_q4(Wv[i4 * 4 + 2], ws, -1.f, 1.f);
    o.w = pack_q4(Wv[i4 * 4 + 3], ws, -1.f, 1.f);
    reinterpret_cast<int4*>(Q)[i4] = o;
}

// ---------------- 4) per-token act_quant of x ----------------
__global__ void k_actq1(const float* __restrict__ x) {
    __shared__ float red[256];
    int t = blockIdx.x;
    const float4* px = reinterpret_cast<const float4*>(x + (size_t)t * H_DIM);
    float4 v0 = px[threadIdx.x * 2], v1 = px[threadIdx.x * 2 + 1];
    float m = fmaxf(fmaxf(fmaxf(fabsf(v0.x), fabsf(v0.y)), fmaxf(fabsf(v0.z), fabsf(v0.w))),
                    fmaxf(fmaxf(fabsf(v1.x), fabsf(v1.y)), fmaxf(fabsf(v1.z), fabsf(v1.w))));
    red[threadIdx.x] = m;
    __syncthreads();
    for (int o = 128; o > 0; o >>= 1) {
        if (threadIdx.x < o) red[threadIdx.x] = fmaxf(red[threadIdx.x], red[threadIdx.x + o]);
        __syncthreads();
    }
    float scale = 128.f / fmaxf(red[0], 1e-5f);
    int p0 = pack_q4(v0, scale, -128.f, 127.f);
    int p1 = pack_q4(v1, scale, -128.f, 127.f);
    reinterpret_cast<int2*>(g_xq + (size_t)t * H_DIM)[threadIdx.x] = make_int2(p0, p1);
    if (threadIdx.x == 0) g_xs[t] = scale;
}

// ---------------- GEMM common geometry ----------------
// BM=128, 128 B-rows, BK=64, 8 warps 2(M)x4(N), warp tile 64x32, 4-stage cp.async,
// ldmatrix fragment loads.
#define SSTRIDE 80
#define STG_SZ  (128 * SSTRIDE)   // 10240 B per operand per stage
#define NSTG    4
#define DSMEM   (2 * NSTG * STG_SZ)  // 81920 B

// ---------------- 5) GEMM1: IMMA, gate+up interleaved, SiLU epilogue ----------------
__global__ __launch_bounds__(256, 2) void k_gemm1() {
    extern __shared__ signed char dyn[];
    const int tid = threadIdx.x, wid = tid >> 5, lane = tid & 31;
    const int gid = lane >> 2, tig = lane & 3;
    const int wm = wid >> 2, wn = wid & 3;
    const int m0 = blockIdx.y * 128, n0 = blockIdx.x * 64;
    const signed char* A = g_xq + (size_t)m0 * H_DIM;

    // ldmatrix per-thread intra-tile offsets
    const int rowA = (lane & 7) + ((lane >> 3) & 1) * 8;   // + matrix row-sel
    const int bytA = ((lane >> 4) & 1) * 16;
    const int rowB = (lane & 7) + ((lane >> 4) & 1) * 8;
    const int bytB = ((lane >> 3) & 1) * 16;
    const uint32_t dynb = smem_u32(dyn);

    int c[4][4][4];
#pragma unroll
    for (int i = 0; i < 4; i++)
#pragma unroll
        for (int j = 0; j < 4; j++)
#pragma unroll
            for (int q = 0; q < 4; q++) c[i][j][q] = 0;

    auto load_stage = [&](int st, int kb) {
        int koff = kb * 64;
        signed char* dA = dyn + st * STG_SZ;
        signed char* dB = dyn + NSTG * STG_SZ + st * STG_SZ;
#pragma unroll
        for (int l = 0; l < 2; l++) {
            int ch = tid + l * 256;
            int r = ch >> 2, c16 = ch & 3;
            CP_ASYNC16(smem_u32(&dA[r * SSTRIDE + c16 * 16]),
                       A + (size_t)r * H_DIM + koff + c16 * 16);
            int n = n0 + (r >> 1);
            const signed char* W = (r & 1) ? g_wqu : g_wqg;
            CP_ASYNC16(smem_u32(&dB[r * SSTRIDE + c16 * 16]),
                       W + (size_t)n * H_DIM + koff + c16 * 16);
        }
    };

    load_stage(0, 0); CP_COMMIT();
    load_stage(1, 1); CP_COMMIT();
    load_stage(2, 2); CP_COMMIT();

    const int NKB = 32;
    for (int kb = 0; kb < NKB; kb++) {
        if (kb < NKB - 2)      { CP_WAIT(2); }
        else if (kb == NKB - 2){ CP_WAIT(1); }
        else                   { CP_WAIT(0); }
        __syncthreads();
        if (kb + 3 < NKB) { load_stage((kb + 3) & 3, kb + 3); CP_COMMIT(); }
        int st = kb & 3;
        uint32_t As = dynb + st * STG_SZ;
        uint32_t Bs = dynb + NSTG * STG_SZ + st * STG_SZ;
#pragma unroll
        for (int ks = 0; ks < 2; ks++) {
            int a[4][4], b[4][2];
#pragma unroll
            for (int mi = 0; mi < 4; mi++) {
                uint32_t ad = As + (uint32_t)(wm * 64 + mi * 16 + rowA) * SSTRIDE + ks * 32 + bytA;
                LDSM_X4(a[mi][0], a[mi][1], a[mi][2], a[mi][3], ad);
            }
#pragma unroll
            for (int np = 0; np < 2; np++) {
                uint32_t bd = Bs + (uint32_t)(wn * 32 + np * 16 + rowB) * SSTRIDE + ks * 32 + bytB;
                LDSM_X4(b[2 * np][0], b[2 * np][1], b[2 * np + 1][0], b[2 * np + 1][1], bd);
            }
#pragma unroll
            for (int mi = 0; mi < 4; mi++)
#pragma unroll
                for (int ni = 0; ni < 4; ni++) MMA_S8(c[mi][ni], a[mi], b[ni]);
        }
    }

    float fg = g_wnorm[0], fu = g_wnorm[1];
#pragma unroll
    for (int mi = 0; mi < 4; mi++) {
        int t1 = m0 + wm * 64 + mi * 16 + gid, t2 = t1 + 8;
        float i1 = 1.0f / g_xs[t1], i2 = 1.0f / g_xs[t2];
#pragma unroll
        for (int ni = 0; ni < 4; ni++) {
            int n = n0 + wn * 16 + ni * 4 + tig;
            float gv1 = (float)c[mi][ni][0] * fg * i1;
            float uv1 = (float)c[mi][ni][1] * fu * i1;
            g_inter[(size_t)t1 * I_DIM + n] = gv1 / (1.0f + __expf(-gv1)) * uv1;
            float gv2 = (float)c[mi][ni][2] * fg * i2;
            float uv2 = (float)c[mi][ni][3] * fu * i2;
            g_inter[(size_t)t2 * I_DIM + n] = gv2 / (1.0f + __expf(-gv2)) * uv2;
        }
    }
}

// ---------------- 6) FWHT-8192 + act_quant #2 (register-chunked) ----------------
__global__ __launch_bounds__(512) void k_fwht() {
    __shared__ float s[8192];
    __shared__ float red[512];
    const int tid = threadIdx.x;
    const int t = blockIdx.x;
    float v[16];
    float4* vv = reinterpret_cast<float4*>(v);

    const float4* src = reinterpret_cast<const float4*>(g_inter + (size_t)t * I_DIM);
#pragma unroll
    for (int i = 0; i < 4; i++) vv[i] = src[tid * 4 + i];
#pragma unroll
    for (int h = 1; h < 16; h <<= 1)
#pragma unroll
        for (int i = 0; i < 16; i++)
            if ((i & h) == 0) {
                float a = v[i], b = v[i + h];
                v[i] = a + b; v[i + h] = a - b;
            }
#pragma unroll
    for (int i = 0; i < 4; i++) reinterpret_cast<float4*>(s)[tid * 4 + i] = vv[i];
    __syncthreads();

    int b2 = (tid & 15) + ((tid >> 4) << 8);
#pragma unroll
    for (int j = 0; j < 16; j++) v[j] = s[b2 + 16 * j];
#pragma unroll
    for (int h = 1; h < 16; h <<= 1)
#pragma unroll
        for (int j = 0; j < 16; j++)
            if ((j & h) == 0) {
                float a = v[j], b = v[j + h];
                v[j] = a + b; v[j + h] = a - b;
            }
#pragma unroll
    for (int j = 0; j < 16; j++) s[b2 + 16 * j] = v[j];
    __syncthreads();

    int b3 = (tid & 255) + ((tid >> 8) << 12);
#pragma unroll
    for (int j = 0; j < 16; j++) v[j] = s[b3 + 256 * j];
#pragma unroll
    for (int h = 1; h < 16; h <<= 1)
#pragma unroll
        for (int j = 0; j < 16; j++)
            if ((j & h) == 0) {
                float a = v[j], b = v[j + h];
                v[j] = a + b; v[j + h] = a - b;
            }
#pragma unroll
    for (int j = 0; j < 16; j++) s[b3 + 256 * j] = v[j];
    __syncthreads();

    const float rn = 1.1048543456039805e-02f;  // 1/sqrt(8192)
    float lo[8], hi[8];
    float m = 0.f;
#pragma unroll
    for (int q = 0; q < 8; q++) {
        float a = s[tid * 8 + q], b = s[tid * 8 + q + 4096];
        float na = (a + b) * rn, nb = (a - b) * rn;
        lo[q] = na; hi[q] = nb;
        m = fmaxf(m, fmaxf(fabsf(na), fabsf(nb)));
    }
    red[tid] = m;
    __syncthreads();
    for (int o = 256; o > 0; o >>= 1) {
        if (tid < o) red[tid] = fmaxf(red[tid], red[tid + o]);
        __syncthreads();
    }
    float scale = 128.f / fmaxf(red[0], 1e-5f);
    float4* lv = reinterpret_cast<float4*>(lo);
    float4* hv = reinterpret_cast<float4*>(hi);
    int2 plo = make_int2(pack_q4(lv[0], scale, -128.f, 127.f),
                         pack_q4(lv[1], scale, -128.f, 127.f));
    int2 phi = make_int2(pack_q4(hv[0], scale, -128.f, 127.f),
                         pack_q4(hv[1], scale, -128.f, 127.f));
    int2* orow = reinterpret_cast<int2*>(g_aq2 + (size_t)t * I_DIM);
    orow[tid] = plo;
    orow[tid + 512] = phi;
    if (tid == 0) g_as2[t] = scale;
}

// ---------------- 7) GEMM2: IMMA down projection ----------------
__global__ __launch_bounds__(256, 2) void k_gemm2(float* __restrict__ out) {
    extern __shared__ signed char dyn[];
    const int tid = threadIdx.x, wid = tid >> 5, lane = tid & 31;
    const int gid = lane >> 2, tig = lane & 3;
    const int wm = wid >> 2, wn = wid & 3;
    const int m0 = blockIdx.y * 128, n0 = blockIdx.x * 128;
    const signed char* A = g_aq2 + (size_t)m0 * I_DIM;
    const signed char* B = g_wqd + (size_t)n0 * I_DIM;

    const int rowA = (lane & 7) + ((lane >> 3) & 1) * 8;
    const int bytA = ((lane >> 4) & 1) * 16;
    const int rowB = (lane & 7) + ((lane >> 4) & 1) * 8;
    const int bytB = ((lane >> 3) & 1) * 16;
    const uint32_t dynb = smem_u32(dyn);

    int c[4][4][4];
#pragma unroll
    for (int i = 0; i < 4; i++)
#pragma unroll
        for (int j = 0; j < 4; j++)
#pragma unroll
            for (int q = 0; q < 4; q++) c[i][j][q] = 0;

    auto load_stage = [&](int st, int kb) {
        int koff = kb * 64;
        signed char* dA = dyn + st * STG_SZ;
        signed char* dB = dyn + NSTG * STG_SZ + st * STG_SZ;
#pragma unroll
        for (int l = 0; l < 2; l++) {
            int ch = tid + l * 256;
            int r = ch >> 2, c16 = ch & 3;
            CP_ASYNC16(smem_u32(&dA[r * SSTRIDE + c16 * 16]),
                       A + (size_t)r * I_DIM + koff + c16 * 16);
            CP_ASYNC16(smem_u32(&dB[r * SSTRIDE + c16 * 16]),
                       B + (size_t)r * I_DIM + koff + c16 * 16);
        }
    };

    load_stage(0, 0); CP_COMMIT();
    load_stage(1, 1); CP_COMMIT();
    load_stage(2, 2); CP_COMMIT();

    const int NKB = 128;
    for (int kb = 0; kb < NKB; kb++) {
        if (kb < NKB - 2)      { CP_WAIT(2); }
        else if (kb == NKB - 2){ CP_WAIT(1); }
        else                   { CP_WAIT(0); }
        __syncthreads();
        if (kb + 3 < NKB) { load_stage((kb + 3) & 3, kb + 3); CP_COMMIT(); }
        int st = kb & 3;
        uint32_t As = dynb + st * STG_SZ;
        uint32_t Bs = dynb + NSTG * STG_SZ + st * STG_SZ;
#pragma unroll
        for (int ks = 0; ks < 2; ks++) {
            int a[4][4], b[4][2];
#pragma unroll
            for (int mi = 0; mi < 4; mi++) {
                uint32_t ad = As + (uint32_t)(wm * 64 + mi * 16 + rowA) * SSTRIDE + ks * 32 + bytA;
                LDSM_X4(a[mi][0], a[mi][1], a[mi][2], a[mi][3], ad);
            }
#pragma unroll
            for (int np = 0; np < 2; np++) {
                uint32_t bd = Bs + (uint32_t)(wn * 32 + np * 16 + rowB) * SSTRIDE + ks * 32 + bytB;
                LDSM_X4(b[2 * np][0], b[2 * np][1], b[2 * np + 1][0], b[2 * np + 1][1], bd);
            }
#pragma unroll
            for (int mi = 0; mi < 4; mi++)
#pragma unroll
                for (int ni = 0; ni < 4; ni++) MMA_S8(c[mi][ni], a[mi], b[ni]);
        }
    }

    float fw = g_wnorm[2];
#pragma unroll
    for (int mi = 0; mi < 4; mi++) {
        int t1 = m0 + wm * 64 + mi * 16 + gid, t2 = t1 + 8;
        float f1 = fw / g_as2[t1], f2 = fw / g_as2[t2];
#pragma unroll
        for (int ni = 0; ni < 4; ni++) {
            int col = n0 + wn * 32 + ni * 8 + tig * 2;
            float2 o1 = make_float2((float)c[mi][ni][0] * f1, (float)c[mi][ni][1] * f1);
            float2 o2 = make_float2((float)c[mi][ni][2] * f2, (float)c[mi][ni][3] * f2);
            *reinterpret_cast<float2*>(&out[(size_t)t1 * H_DIM + col]) = o1;
            *reinterpret_cast<float2*>(&out[(size_t)t2 * H_DIM + col]) = o2;
        }
    }
}

// ---------------- launch ----------------
extern "C" void kernel_launch(void* const* d_in, const int* in_sizes, int n_in,
                              void* d_out, int out_size) {
    const float* x  = (const float*)d_in[0];
    const float* wg = (const float*)d_in[1];
    const float* wu = (const float*)d_in[2];
    const float* wd = (const float*)d_in[3];
    float* out = (float*)d_out;

    static int configured = 0;
    if (!configured) {
        cudaFuncSetAttribute(k_gemm1, cudaFuncAttributeMaxDynamicSharedMemorySize, DSMEM);
        cudaFuncSetAttribute(k_gemm2, cudaFuncAttributeMaxDynamicSharedMemorySize, DSMEM);
        configured = 1;
    }

    k_wabs<<<dim3(1024, 3), 256>>>(wg, wu, wd);
    k_wfin<<<3, 1024>>>();
    k_wquant<<<dim3(4096, 3), 256>>>(wg, wu, wd);
    k_actq1<<<T_TOK, 256>>>(x);
    k_gemm1<<<dim3(I_DIM / 64, T_TOK / 128), 256, DSMEM>>>();
    k_fwht<<<T_TOK, 512>>>();
    k_gemm2<<<dim3(H_DIM / 128, T_TOK / 128), 256, DSMEM>>>(out);
}